// round 16
// baseline (speedup 1.0000x reference)
#include <cuda_runtime.h>

// Sinkhorn: 65536 matrices of 36x36, 21 iterations of row/col log-normalization,
// temperature 0.01, output exp(log_alpha).
//
// Base-2 potential form: matrix = y - U_i - V_j, y = input * (100*log2 e).
//   row pass: U_i = lse2_j(y_ij - V_j);  col pass: V_j = lse2_i(y_ij - U_i)
// start V=0; after 21 (row,col) pairs, out = 2^(y - U - V).
//
// R16 = R11's shift math on R9's resource envelope (stride 37, occ 3, cap 75
// regs -> no spills, unlike R11 whose occ-4 56-reg cap caused the L2=59%
// spill collapse). Iters 0-2: exact max (large transient drift). Iters >= 3:
// shift the lse by the thread's previous own potential -> the ~110-instr
// exp-free max prefix after each barrier disappears and the MUFU pipe starts
// immediately. Window check (s in 2^-100..2^100) + exact-max fallback keeps
// it correct for arbitrary drift. No t[36]/yreg arrays: ~50 regs.

#define NMAT_PER_BLOCK 8
#define THREADS 288            // 8 groups * 36 = 9 full warps
#define NDIM 36
#define STRIDE 37              // conflict-free rows & columns (scalar LDS)
#define MAT_SMEM (NDIM * STRIDE)
#define MAT_ELEMS (NDIM * NDIM)
#define SCALE 144.269504088896340736f   // 100 * log2(e)
#define NITERS 21
#define WIN_LO 7.8886e-31f     // 2^-100
#define WIN_HI 1.2677e+30f     // 2^100

__device__ __forceinline__ float ex2f(float x) {
    float y; asm("ex2.approx.ftz.f32 %0, %1;" : "=f"(y) : "f"(x)); return y;
}
__device__ __forceinline__ float lg2f(float x) {
    float y; asm("lg2.approx.ftz.f32 %0, %1;" : "=f"(y) : "f"(x)); return y;
}
__device__ __forceinline__ bool in_window(float s) {
    return (s > WIN_LO) && (s < WIN_HI);   // false for 0, inf, NaN, negative
}

__global__ __launch_bounds__(THREADS, 3)
void sinkhorn_kernel(const float* __restrict__ in, float* __restrict__ out)
{
    __shared__ float sy[NMAT_PER_BLOCK * MAT_SMEM];
    __shared__ __align__(16) float sU[NMAT_PER_BLOCK * NDIM];
    __shared__ __align__(16) float sV[NMAT_PER_BLOCK * NDIM];

    const int tid = threadIdx.x;
    const long long base = (long long)blockIdx.x * (NMAT_PER_BLOCK * MAT_ELEMS);

    // ---- load: coalesced float4 from global, scatter into padded smem, fused scale
    {
        const float4* in4 = (const float4*)(in + base);
        for (int k = tid; k < (NMAT_PER_BLOCK * MAT_ELEMS) / 4; k += THREADS) {
            float4 v = in4[k];
            float vals[4] = {v.x, v.y, v.z, v.w};
            int e = k * 4;
            #pragma unroll
            for (int q = 0; q < 4; q++) {
                int idx = e + q;
                int g   = idx / MAT_ELEMS;
                int rem = idx - g * MAT_ELEMS;
                int r   = rem / NDIM;
                int c   = rem - r * NDIM;
                sy[g * MAT_SMEM + r * STRIDE + c] = vals[q] * SCALE;
            }
        }
    }
    sV[tid] = 0.0f;                       // 288 == THREADS
    __syncthreads();

    const int g = tid / NDIM;          // which matrix in this block
    const int l = tid - g * NDIM;      // row (row pass) / col (col pass) index

    const float4* U4 = (const float4*)&sU[g * NDIM];
    const float4* V4 = (const float4*)&sV[g * NDIM];
    float* U = &sU[g * NDIM];
    float* V = &sV[g * NDIM];
    const float* srow = &sy[g * MAT_SMEM + l * STRIDE];
    const float* scol = &sy[g * MAT_SMEM + l];

    // ---- helpers (forceinline lambdas; exp consumes its argument immediately)
    auto row_sum = [&](float m) -> float {
        float s0 = 0.f, s1 = 0.f, s2 = 0.f, s3 = 0.f;
        #pragma unroll
        for (int q = 0; q < 9; q++) {
            float4 v = V4[q];                       // broadcast across the group
            s0 += ex2f((srow[4*q+0] - m) - v.x);
            s1 += ex2f((srow[4*q+1] - m) - v.y);
            s2 += ex2f((srow[4*q+2] - m) - v.z);
            s3 += ex2f((srow[4*q+3] - m) - v.w);
        }
        return (s0 + s1) + (s2 + s3);
    };
    auto row_max = [&]() -> float {
        float m0 = -3e38f, m1 = -3e38f, m2 = -3e38f, m3 = -3e38f;
        #pragma unroll
        for (int q = 0; q < 9; q++) {
            float4 v = V4[q];
            m0 = fmaxf(m0, srow[4*q+0] - v.x);  m1 = fmaxf(m1, srow[4*q+1] - v.y);
            m2 = fmaxf(m2, srow[4*q+2] - v.z);  m3 = fmaxf(m3, srow[4*q+3] - v.w);
        }
        return fmaxf(fmaxf(m0, m1), fmaxf(m2, m3));
    };
    auto col_sum = [&](float m) -> float {
        float s0 = 0.f, s1 = 0.f, s2 = 0.f, s3 = 0.f;
        #pragma unroll
        for (int q = 0; q < 9; q++) {
            float4 u = U4[q];
            s0 += ex2f((scol[(4*q+0) * STRIDE] - m) - u.x);
            s1 += ex2f((scol[(4*q+1) * STRIDE] - m) - u.y);
            s2 += ex2f((scol[(4*q+2) * STRIDE] - m) - u.z);
            s3 += ex2f((scol[(4*q+3) * STRIDE] - m) - u.w);
        }
        return (s0 + s1) + (s2 + s3);
    };
    auto col_max = [&]() -> float {
        float m0 = -3e38f, m1 = -3e38f, m2 = -3e38f, m3 = -3e38f;
        #pragma unroll
        for (int q = 0; q < 9; q++) {
            float4 u = U4[q];
            m0 = fmaxf(m0, scol[(4*q+0) * STRIDE] - u.x);
            m1 = fmaxf(m1, scol[(4*q+1) * STRIDE] - u.y);
            m2 = fmaxf(m2, scol[(4*q+2) * STRIDE] - u.z);
            m3 = fmaxf(m3, scol[(4*q+3) * STRIDE] - u.w);
        }
        return fmaxf(fmaxf(m0, m1), fmaxf(m2, m3));
    };

    float uown = 0.0f, vown = 0.0f;

    #pragma unroll 1
    for (int it = 0; it < NITERS; it++) {
        // ---- row pass: U[l] = m + log2(sum_j 2^(y[l][j] - V[j] - m))
        {
            float m = uown, s = 0.0f;
            bool exact = (it < 3);
            if (!exact) {                 // fast path: no max phase at all
                s = row_sum(m);
                exact = !in_window(s);    // rare large drift -> redo exactly
            }
            if (exact) {
                m = row_max();
                s = row_sum(m);
            }
            uown = m + lg2f(s);
            U[l] = uown;
        }
        __syncthreads();

        // ---- col pass: V[l] = m + log2(sum_i 2^(y[i][l] - U[i] - m))
        {
            float m = vown, s = 0.0f;
            bool exact = (it < 3);
            if (!exact) {
                s = col_sum(m);
                exact = !in_window(s);
            }
            if (exact) {
                m = col_max();
                s = col_sum(m);
            }
            vown = m + lg2f(s);
            V[l] = vown;
        }
        __syncthreads();
    }

    // ---- output: overwrite my row of sy with 2^(y - U - V)
    {
        const float u = uown;
        float* od = &sy[g * MAT_SMEM + l * STRIDE];
        #pragma unroll
        for (int q = 0; q < 9; q++) {
            float4 v = V4[q];
            float r0 = ex2f((od[4*q+0] - u) - v.x);
            float r1 = ex2f((od[4*q+1] - u) - v.y);
            float r2 = ex2f((od[4*q+2] - u) - v.z);
            float r3 = ex2f((od[4*q+3] - u) - v.w);
            od[4*q+0] = r0; od[4*q+1] = r1; od[4*q+2] = r2; od[4*q+3] = r3;
        }
    }
    __syncthreads();
    {
        float4* out4 = (float4*)(out + base);
        for (int k = tid; k < (NMAT_PER_BLOCK * MAT_ELEMS) / 4; k += THREADS) {
            int e = k * 4;
            float r[4];
            #pragma unroll
            for (int q = 0; q < 4; q++) {
                int idx = e + q;
                int gg  = idx / MAT_ELEMS;
                int rem = idx - gg * MAT_ELEMS;
                int rr  = rem / NDIM;
                int cc  = rem - rr * NDIM;
                r[q] = sy[gg * MAT_SMEM + rr * STRIDE + cc];
            }
            out4[k] = make_float4(r[0], r[1], r[2], r[3]);
        }
    }
}

extern "C" void kernel_launch(void* const* d_in, const int* in_sizes, int n_in,
                              void* d_out, int out_size) {
    const float* in = (const float*)d_in[0];
    float* out = (float*)d_out;
    int num_mats = in_sizes[0] / MAT_ELEMS;          // 65536
    int grid = num_mats / NMAT_PER_BLOCK;            // 8192
    sinkhorn_kernel<<<grid, THREADS>>>(in, out);
}

// round 17
// speedup vs baseline: 1.1794x; 1.1794x over previous
#include <cuda_runtime.h>

// Sinkhorn: 65536 matrices of 36x36, 21 iterations of row/col log-normalization,
// temperature 0.01, output exp(log_alpha).
//
// Base-2 potential form: matrix = y - U_i - V_j, y = input * (100*log2 e).
//   row pass: U_i = lse2_j(y_ij - V_j);  col pass: V_j = lse2_i(y_ij - U_i)
// start V=0; after 21 (row,col) pairs, out = 2^(y - U - V).
//
// R17 = R9 (dense, branch-free, exact, occ 3, stride 37) with each pass's lse
// computed as an exact TWO-SEGMENT online lse: segment A (20 elems) starts its
// exp burst after ~60 instructions (vs ~110 for the monolithic max phase),
// segment B uses the running (= global) max, and the segments combine with one
// extra ex2 + FMA:  s = sA * 2^(mA - M) + sB.  This halves the post-barrier
// MUFU bubble while keeping the math exact (all exp args <= 0, segment sums
// <= 20, rescale <= 1: no overflow; underflow identical to reference's
// max-shifted lse). t[] shrinks 36 -> 20 (regs ~55-60, no spill risk).

#define NMAT_PER_BLOCK 8
#define THREADS 288            // 8 groups * 36 = 9 full warps
#define NDIM 36
#define STRIDE 37              // conflict-free rows & columns
#define MAT_SMEM (NDIM * STRIDE)
#define MAT_ELEMS (NDIM * NDIM)
#define SCALE 144.269504088896340736f   // 100 * log2(e)
#define NITERS 21
#define SEGA 20                // elements 0..19  (5 float4 groups)
                               // segment B: elements 20..35 (4 float4 groups)

__device__ __forceinline__ float ex2f(float x) {
    float y; asm("ex2.approx.ftz.f32 %0, %1;" : "=f"(y) : "f"(x)); return y;
}
__device__ __forceinline__ float lg2f(float x) {
    float y; asm("lg2.approx.ftz.f32 %0, %1;" : "=f"(y) : "f"(x)); return y;
}

__global__ __launch_bounds__(THREADS, 3)
void sinkhorn_kernel(const float* __restrict__ in, float* __restrict__ out)
{
    __shared__ float sy[NMAT_PER_BLOCK * MAT_SMEM];
    __shared__ __align__(16) float sU[NMAT_PER_BLOCK * NDIM];
    __shared__ __align__(16) float sV[NMAT_PER_BLOCK * NDIM];

    const int tid = threadIdx.x;
    const long long base = (long long)blockIdx.x * (NMAT_PER_BLOCK * MAT_ELEMS);

    // ---- load: coalesced float4 from global, scatter into padded smem, fused scale
    {
        const float4* in4 = (const float4*)(in + base);
        for (int k = tid; k < (NMAT_PER_BLOCK * MAT_ELEMS) / 4; k += THREADS) {
            float4 v = in4[k];
            float vals[4] = {v.x, v.y, v.z, v.w};
            int e = k * 4;
            #pragma unroll
            for (int q = 0; q < 4; q++) {
                int idx = e + q;
                int g   = idx / MAT_ELEMS;
                int rem = idx - g * MAT_ELEMS;
                int r   = rem / NDIM;
                int c   = rem - r * NDIM;
                sy[g * MAT_SMEM + r * STRIDE + c] = vals[q] * SCALE;
            }
        }
    }
    sV[tid] = 0.0f;                       // 288 == THREADS
    __syncthreads();

    const int g = tid / NDIM;          // which matrix in this block
    const int l = tid - g * NDIM;      // row (row pass) / col (col pass) index

    const float4* U4 = (const float4*)&sU[g * NDIM];
    const float4* V4 = (const float4*)&sV[g * NDIM];
    float* U = &sU[g * NDIM];
    float* V = &sV[g * NDIM];
    const float* srow = &sy[g * MAT_SMEM + l * STRIDE];
    const float* scol = &sy[g * MAT_SMEM + l];

    #pragma unroll 1
    for (int it = 0; it < NITERS; it++) {
        // ---- row pass: U[l] = lse2_j(y[l][j] - V[j])  (two-segment online)
        {
            float t[SEGA];
            // segment A: j = 0..19
            float m0 = -1e30f, m1 = -1e30f, m2 = -1e30f, m3 = -1e30f;
            #pragma unroll
            for (int q = 0; q < 5; q++) {
                float4 v = V4[q];                 // broadcast across the group
                t[4*q+0] = srow[4*q+0] - v.x;
                t[4*q+1] = srow[4*q+1] - v.y;
                t[4*q+2] = srow[4*q+2] - v.z;
                t[4*q+3] = srow[4*q+3] - v.w;
                m0 = fmaxf(m0, t[4*q+0]);  m1 = fmaxf(m1, t[4*q+1]);
                m2 = fmaxf(m2, t[4*q+2]);  m3 = fmaxf(m3, t[4*q+3]);
            }
            float mA = fmaxf(fmaxf(m0, m1), fmaxf(m2, m3));
            float s0 = 0.f, s1 = 0.f, s2 = 0.f, s3 = 0.f;
            #pragma unroll
            for (int q = 0; q < 5; q++) {         // exp burst starts here (early)
                s0 += ex2f(t[4*q+0] - mA);
                s1 += ex2f(t[4*q+1] - mA);
                s2 += ex2f(t[4*q+2] - mA);
                s3 += ex2f(t[4*q+3] - mA);
            }
            float sA = (s0 + s1) + (s2 + s3);
            // segment B: j = 20..35 (reuse t[0..15])
            m0 = -1e30f; m1 = -1e30f; m2 = -1e30f; m3 = -1e30f;
            #pragma unroll
            for (int q = 0; q < 4; q++) {
                float4 v = V4[5 + q];
                t[4*q+0] = srow[20 + 4*q+0] - v.x;
                t[4*q+1] = srow[20 + 4*q+1] - v.y;
                t[4*q+2] = srow[20 + 4*q+2] - v.z;
                t[4*q+3] = srow[20 + 4*q+3] - v.w;
                m0 = fmaxf(m0, t[4*q+0]);  m1 = fmaxf(m1, t[4*q+1]);
                m2 = fmaxf(m2, t[4*q+2]);  m3 = fmaxf(m3, t[4*q+3]);
            }
            float M = fmaxf(mA, fmaxf(fmaxf(m0, m1), fmaxf(m2, m3)));  // global max
            s0 = 0.f; s1 = 0.f; s2 = 0.f; s3 = 0.f;
            #pragma unroll
            for (int q = 0; q < 4; q++) {
                s0 += ex2f(t[4*q+0] - M);
                s1 += ex2f(t[4*q+1] - M);
                s2 += ex2f(t[4*q+2] - M);
                s3 += ex2f(t[4*q+3] - M);
            }
            float sB = (s0 + s1) + (s2 + s3);
            float s = __fmaf_rn(sA, ex2f(mA - M), sB);   // exact combine
            U[l] = M + lg2f(s);
        }
        __syncthreads();

        // ---- col pass: V[l] = lse2_i(y[i][l] - U[i])  (two-segment online)
        {
            float t[SEGA];
            float m0 = -1e30f, m1 = -1e30f, m2 = -1e30f, m3 = -1e30f;
            #pragma unroll
            for (int q = 0; q < 5; q++) {
                float4 u = U4[q];                 // broadcast across the group
                t[4*q+0] = scol[(4*q+0) * STRIDE] - u.x;
                t[4*q+1] = scol[(4*q+1) * STRIDE] - u.y;
                t[4*q+2] = scol[(4*q+2) * STRIDE] - u.z;
                t[4*q+3] = scol[(4*q+3) * STRIDE] - u.w;
                m0 = fmaxf(m0, t[4*q+0]);  m1 = fmaxf(m1, t[4*q+1]);
                m2 = fmaxf(m2, t[4*q+2]);  m3 = fmaxf(m3, t[4*q+3]);
            }
            float mA = fmaxf(fmaxf(m0, m1), fmaxf(m2, m3));
            float s0 = 0.f, s1 = 0.f, s2 = 0.f, s3 = 0.f;
            #pragma unroll
            for (int q = 0; q < 5; q++) {
                s0 += ex2f(t[4*q+0] - mA);
                s1 += ex2f(t[4*q+1] - mA);
                s2 += ex2f(t[4*q+2] - mA);
                s3 += ex2f(t[4*q+3] - mA);
            }
            float sA = (s0 + s1) + (s2 + s3);
            m0 = -1e30f; m1 = -1e30f; m2 = -1e30f; m3 = -1e30f;
            #pragma unroll
            for (int q = 0; q < 4; q++) {
                float4 u = U4[5 + q];
                t[4*q+0] = scol[(20 + 4*q+0) * STRIDE] - u.x;
                t[4*q+1] = scol[(20 + 4*q+1) * STRIDE] - u.y;
                t[4*q+2] = scol[(20 + 4*q+2) * STRIDE] - u.z;
                t[4*q+3] = scol[(20 + 4*q+3) * STRIDE] - u.w;
                m0 = fmaxf(m0, t[4*q+0]);  m1 = fmaxf(m1, t[4*q+1]);
                m2 = fmaxf(m2, t[4*q+2]);  m3 = fmaxf(m3, t[4*q+3]);
            }
            float M = fmaxf(mA, fmaxf(fmaxf(m0, m1), fmaxf(m2, m3)));
            s0 = 0.f; s1 = 0.f; s2 = 0.f; s3 = 0.f;
            #pragma unroll
            for (int q = 0; q < 4; q++) {
                s0 += ex2f(t[4*q+0] - M);
                s1 += ex2f(t[4*q+1] - M);
                s2 += ex2f(t[4*q+2] - M);
                s3 += ex2f(t[4*q+3] - M);
            }
            float sB = (s0 + s1) + (s2 + s3);
            float s = __fmaf_rn(sA, ex2f(mA - M), sB);
            V[l] = M + lg2f(s);
        }
        __syncthreads();
    }

    // ---- output: overwrite my row of sy with 2^(y - U - V)
    {
        const float u = U[l];
        float* od = &sy[g * MAT_SMEM + l * STRIDE];
        #pragma unroll
        for (int q = 0; q < 9; q++) {
            float4 v = V4[q];
            float r0 = ex2f((od[4*q+0] - u) - v.x);
            float r1 = ex2f((od[4*q+1] - u) - v.y);
            float r2 = ex2f((od[4*q+2] - u) - v.z);
            float r3 = ex2f((od[4*q+3] - u) - v.w);
            od[4*q+0] = r0; od[4*q+1] = r1; od[4*q+2] = r2; od[4*q+3] = r3;
        }
    }
    __syncthreads();
    {
        float4* out4 = (float4*)(out + base);
        for (int k = tid; k < (NMAT_PER_BLOCK * MAT_ELEMS) / 4; k += THREADS) {
            int e = k * 4;
            float r[4];
            #pragma unroll
            for (int q = 0; q < 4; q++) {
                int idx = e + q;
                int gg  = idx / MAT_ELEMS;
                int rem = idx - gg * MAT_ELEMS;
                int rr  = rem / NDIM;
                int cc  = rem - rr * NDIM;
                r[q] = sy[gg * MAT_SMEM + rr * STRIDE + cc];
            }
            out4[k] = make_float4(r[0], r[1], r[2], r[3]);
        }
    }
}

extern "C" void kernel_launch(void* const* d_in, const int* in_sizes, int n_in,
                              void* d_out, int out_size) {
    const float* in = (const float*)d_in[0];
    float* out = (float*)d_out;
    int num_mats = in_sizes[0] / MAT_ELEMS;          // 65536
    int grid = num_mats / NMAT_PER_BLOCK;            // 8192
    sinkhorn_kernel<<<grid, THREADS>>>(in, out);
}